// round 9
// baseline (speedup 1.0000x reference)
#include <cuda_runtime.h>
#include <cstdint>

#define NB      16384
#define DTC     0.1f
#define FPB     32
#define THREADS 128
#define FS      833              // filter stride (words), odd -> conflict-free STS
#define RSTEP   52               // row stride: 52 step slots (max half size)
#define SMEM_WORDS (32 * FS)     // 26656
#define SMEM_BYTES (SMEM_WORDS * 4)   // 106624 B -> 2 blocks/SM

__constant__ int ROWMAP[22] = {0,1,2,3,4,5,
                               6,7,8,9, 7,10,11,12, 8,11,13,14, 9,12,14,15};

struct St  { float x0,x1,x2,x3,p00,p01,p02,p03,p11,p12,p13,p22,p23,p33; };
struct Cst { float q00,q01,q02,q03,q11,q12,q13,q22,q23,q33,r00,r01,r11; };

// one exact-collapsed UKF step (affine motion => linear KF);
// Pn via K*A_c^T (== K S K^T since K = A_c S^{-1}); stages 16 unique rows.
__device__ __forceinline__ void ukf_step(
    St& s, const Cst& c, float z0, float z1, float ux, float uy,
    float* __restrict__ stage_f, int sp)
{
    const float xp0 = s.x0 + DTC * s.x2 + 0.5f * DTC * DTC * ux;
    const float xp1 = s.x1 + DTC * s.x3 + 0.5f * DTC * DTC * uy;
    const float xp2 = s.x2 + DTC * ux;
    const float xp3 = s.x3 + DTC * uy;

    const float a02 = s.p02 + DTC * s.p22;
    const float a03 = s.p03 + DTC * s.p23;
    const float a12 = s.p12 + DTC * s.p23;
    const float a13 = s.p13 + DTC * s.p33;
    const float a00 = s.p00 + DTC * s.p02 + DTC * a02;
    const float a11 = s.p11 + DTC * s.p13 + DTC * a13;
    const float a01 = s.p01 + DTC * s.p03 + DTC * a12;

    const float s00 = a00 + c.r00;
    const float s01 = a01 + c.r01;
    const float s11 = a11 + c.r11;
    const float idet = __fdividef(1.0f, s00 * s11 - s01 * s01);
    const float i00 =  s11 * idet;
    const float i01 = -s01 * idet;
    const float i11 =  s00 * idet;

    const float K00 = a00 * i00 + a01 * i01, K01 = a00 * i01 + a01 * i11;
    const float K10 = a01 * i00 + a11 * i01, K11 = a01 * i01 + a11 * i11;
    const float K20 = a02 * i00 + a12 * i01, K21 = a02 * i01 + a12 * i11;
    const float K30 = a03 * i00 + a13 * i01, K31 = a03 * i01 + a13 * i11;

    const float in0 = z0 - xp0, in1 = z1 - xp1;
    const float xn0 = xp0 + K00 * in0 + K01 * in1;
    const float xn1 = xp1 + K10 * in0 + K11 * in1;
    const float xn2 = xp2 + K20 * in0 + K21 * in1;
    const float xn3 = xp3 + K30 * in0 + K31 * in1;

    s.p00 = (a00 + c.q00) - (K00 * a00 + K01 * a01);
    s.p01 = (a01 + c.q01) - (K00 * a01 + K01 * a11);
    s.p02 = (a02 + c.q02) - (K00 * a02 + K01 * a12);
    s.p03 = (a03 + c.q03) - (K00 * a03 + K01 * a13);
    s.p11 = (a11 + c.q11) - (K10 * a01 + K11 * a11);
    s.p12 = (a12 + c.q12) - (K10 * a02 + K11 * a12);
    s.p13 = (a13 + c.q13) - (K10 * a03 + K11 * a13);
    s.p22 = (s.p22 + c.q22) - (K20 * a02 + K21 * a12);
    s.p23 = (s.p23 + c.q23) - (K20 * a03 + K21 * a13);
    s.p33 = (s.p33 + c.q33) - (K30 * a03 + K31 * a13);
    s.x0 = xn0; s.x1 = xn1; s.x2 = xn2; s.x3 = xn3;

    stage_f[ 0 * RSTEP + sp] = xp0;   stage_f[ 1 * RSTEP + sp] = xp1;
    stage_f[ 2 * RSTEP + sp] = xn0;   stage_f[ 3 * RSTEP + sp] = xn1;
    stage_f[ 4 * RSTEP + sp] = xn2;   stage_f[ 5 * RSTEP + sp] = xn3;
    stage_f[ 6 * RSTEP + sp] = s.p00; stage_f[ 7 * RSTEP + sp] = s.p01;
    stage_f[ 8 * RSTEP + sp] = s.p02; stage_f[ 9 * RSTEP + sp] = s.p03;
    stage_f[10 * RSTEP + sp] = s.p11; stage_f[11 * RSTEP + sp] = s.p12;
    stage_f[12 * RSTEP + sp] = s.p13; stage_f[13 * RSTEP + sp] = s.p22;
    stage_f[14 * RSTEP + sp] = s.p23; stage_f[15 * RSTEP + sp] = s.p33;
}

// run one 8-step chunk from prefetched registers
__device__ __forceinline__ void run_chunk8(
    St& s, const Cst& c, float* __restrict__ stage_f, int slot0,
    float4 z0a, float4 z0b, float4 z1a, float4 z1b,
    float4 c0, float4 c1, float4 c2, float4 c3)
{
    const float z0s[8] = {z0a.x,z0a.y,z0a.z,z0a.w, z0b.x,z0b.y,z0b.z,z0b.w};
    const float z1s[8] = {z1a.x,z1a.y,z1a.z,z1a.w, z1b.x,z1b.y,z1b.z,z1b.w};
    const float uxs[8] = {c0.x,c0.z,c1.x,c1.z, c2.x,c2.z,c3.x,c3.z};
    const float uys[8] = {c0.y,c0.w,c1.y,c1.w, c2.y,c2.w,c3.y,c3.w};
#pragma unroll
    for (int sp = 0; sp < 8; sp++)
        ukf_step(s, c, z0s[sp], z1s[sp], uxs[sp], uys[sp], stage_f, slot0 + sp);
}

// flush one half: G float4-groups per output row, global step base sglob
template <int G, int NIT>
__device__ __forceinline__ void flush_half(
    const float* __restrict__ sm, float* __restrict__ preds,
    float* __restrict__ states, float* __restrict__ covs,
    int b0, int tid, int sglob)
{
    const int TOT = 32 * 22 * G;
#pragma unroll 1
    for (int k = 0; k < NIT; k++) {
        const int id = tid + THREADS * k;
        if (TOT % THREADS != 0) { if (id >= TOT) break; }
        const int f   = id / (22 * G);
        const int rem = id % (22 * G);
        const int R   = rem / G;
        const int g   = rem % G;
        const float* src = sm + f * FS + ROWMAP[R] * RSTEP + 4 * g;
        float4 v = make_float4(src[0], src[1], src[2], src[3]);
        const int gb = b0 + f;
        float* dst = (R < 2) ? preds  + (size_t)gb * 200  + R * 100
                   : (R < 6) ? states + (size_t)gb * 400  + (R - 2) * 100
                             : covs   + (size_t)gb * 1600 + (R - 6) * 100;
        *reinterpret_cast<float4*>(dst + sglob + 4 * g) = v;
    }
}

__global__ __launch_bounds__(THREADS, 1) void ukf_kernel(
    const float* __restrict__ meas, const float* __restrict__ state0,
    const float* __restrict__ cov0, const float* __restrict__ ctrl,
    const float* __restrict__ Qm,   const float* __restrict__ Rm,
    float* __restrict__ preds, float* __restrict__ states, float* __restrict__ covs)
{
    extern __shared__ float sm[];
    const int tid = threadIdx.x;
    const int b0  = blockIdx.x * FPB;

    St s;  Cst c;
    const float* mrow = nullptr;
    const float* crow = nullptr;
    float* stage_f = nullptr;
    float4 pz0a, pz0b, pz1a, pz1b, pc0, pc1, pc2, pc3;

    if (tid < 32) {
        const int b = b0 + tid;
        float4 xv = *reinterpret_cast<const float4*>(state0 + (size_t)b * 4);
        s.x0 = xv.x; s.x1 = xv.y; s.x2 = xv.z; s.x3 = xv.w;
        const float4* pv = reinterpret_cast<const float4*>(cov0 + (size_t)b * 16);
        float4 r0 = pv[0], r1 = pv[1], r2 = pv[2], r3 = pv[3];
        s.p00 = r0.x; s.p01 = r0.y; s.p02 = r0.z; s.p03 = r0.w;
        s.p11 = r1.y; s.p12 = r1.z; s.p13 = r1.w;
        s.p22 = r2.z; s.p23 = r2.w; s.p33 = r3.w;

        c.q00 = Qm[0];  c.q01 = Qm[1];  c.q02 = Qm[2];  c.q03 = Qm[3];
        c.q11 = Qm[5];  c.q12 = Qm[6];  c.q13 = Qm[7];
        c.q22 = Qm[10]; c.q23 = Qm[11]; c.q33 = Qm[15];
        c.r00 = Rm[0];  c.r01 = Rm[1];  c.r11 = Rm[3];

        mrow = meas + (size_t)b * 200;
        crow = ctrl + (size_t)b * 200;
        stage_f = sm + tid * FS;

        // prefetch chunk 0
        pz0a = *reinterpret_cast<const float4*>(mrow);
        pz0b = *reinterpret_cast<const float4*>(mrow + 4);
        pz1a = *reinterpret_cast<const float4*>(mrow + 100);
        pz1b = *reinterpret_cast<const float4*>(mrow + 104);
        pc0  = *reinterpret_cast<const float4*>(crow);
        pc1  = *reinterpret_cast<const float4*>(crow + 4);
        pc2  = *reinterpret_cast<const float4*>(crow + 8);
        pc3  = *reinterpret_cast<const float4*>(crow + 12);

        // ---- H1: chunks 0..5 (steps 0..47), slots 0..47 ----
#pragma unroll 1
        for (int ch = 0; ch < 6; ch++) {
            float4 z0a = pz0a, z0b = pz0b, z1a = pz1a, z1b = pz1b;
            float4 c0 = pc0, c1 = pc1, c2 = pc2, c3 = pc3;
            const int s0n = (ch + 1) * 8;     // 8..48, all full chunks valid
            pz0a = *reinterpret_cast<const float4*>(mrow + s0n);
            pz0b = *reinterpret_cast<const float4*>(mrow + s0n + 4);
            pz1a = *reinterpret_cast<const float4*>(mrow + 100 + s0n);
            pz1b = *reinterpret_cast<const float4*>(mrow + 104 + s0n);
            pc0  = *reinterpret_cast<const float4*>(crow + 2 * s0n);
            pc1  = *reinterpret_cast<const float4*>(crow + 2 * s0n + 4);
            pc2  = *reinterpret_cast<const float4*>(crow + 2 * s0n + 8);
            pc3  = *reinterpret_cast<const float4*>(crow + 2 * s0n + 12);
            run_chunk8(s, c, stage_f, ch * 8, z0a, z0b, z1a, z1b, c0, c1, c2, c3);
        }
    }

    __syncthreads();                         // H1 staging complete
    flush_half<12, 66>(sm, preds, states, covs, b0, tid, 0);
    __syncthreads();                         // staging reusable

    if (tid < 32) {
        // ---- H2: chunks 6..11 (steps 48..95), slots 0..47; tail 96..99 slots 48..51 ----
#pragma unroll 1
        for (int ch = 6; ch < 12; ch++) {
            float4 z0a = pz0a, z0b = pz0b, z1a = pz1a, z1b = pz1b;
            float4 c0 = pc0, c1 = pc1, c2 = pc2, c3 = pc3;
            if (ch < 11) {
                const int s0n = (ch + 1) * 8;
                pz0a = *reinterpret_cast<const float4*>(mrow + s0n);
                pz0b = *reinterpret_cast<const float4*>(mrow + s0n + 4);
                pz1a = *reinterpret_cast<const float4*>(mrow + 100 + s0n);
                pz1b = *reinterpret_cast<const float4*>(mrow + 104 + s0n);
                pc0  = *reinterpret_cast<const float4*>(crow + 2 * s0n);
                pc1  = *reinterpret_cast<const float4*>(crow + 2 * s0n + 4);
                pc2  = *reinterpret_cast<const float4*>(crow + 2 * s0n + 8);
                pc3  = *reinterpret_cast<const float4*>(crow + 2 * s0n + 12);
            } else {
                // tail prefetch (4 steps at s0=96): only in-bounds pieces
                pz0a = *reinterpret_cast<const float4*>(mrow + 96);
                pz1a = *reinterpret_cast<const float4*>(mrow + 196);
                pc0  = *reinterpret_cast<const float4*>(crow + 192);
                pc1  = *reinterpret_cast<const float4*>(crow + 196);
            }
            run_chunk8(s, c, stage_f, (ch - 6) * 8, z0a, z0b, z1a, z1b, c0, c1, c2, c3);
        }
        // tail: 4 steps, slots 48..51
        {
            const float z0s[4] = {pz0a.x, pz0a.y, pz0a.z, pz0a.w};
            const float z1s[4] = {pz1a.x, pz1a.y, pz1a.z, pz1a.w};
            const float uxs[4] = {pc0.x, pc0.z, pc1.x, pc1.z};
            const float uys[4] = {pc0.y, pc0.w, pc1.y, pc1.w};
#pragma unroll
            for (int sp = 0; sp < 4; sp++)
                ukf_step(s, c, z0s[sp], z1s[sp], uxs[sp], uys[sp],
                         stage_f, 48 + sp);
        }
    }

    __syncthreads();                         // H2 staging complete
    flush_half<13, 72>(sm, preds, states, covs, b0, tid, 48);
}

extern "C" void kernel_launch(void* const* d_in, const int* in_sizes, int n_in,
                              void* d_out, int out_size)
{
    const float* meas  = (const float*)d_in[0];
    const float* state = (const float*)d_in[1];
    const float* cov   = (const float*)d_in[2];
    const float* ctrl  = (const float*)d_in[3];
    const float* Q     = (const float*)d_in[4];
    const float* R     = (const float*)d_in[5];

    float* out    = (float*)d_out;
    float* preds  = out;                         // 16384*2*100
    float* states = preds  + (size_t)NB * 200;   // 16384*4*100
    float* covs   = states + (size_t)NB * 400;   // 16384*16*100

    static int smem_set = 0;
    if (!smem_set) {
        cudaFuncSetAttribute(ukf_kernel,
                             cudaFuncAttributeMaxDynamicSharedMemorySize, SMEM_BYTES);
        smem_set = 1;
    }

    ukf_kernel<<<NB / FPB, THREADS, SMEM_BYTES>>>(meas, state, cov, ctrl, Q, R,
                                                  preds, states, covs);
}

// round 10
// speedup vs baseline: 1.0032x; 1.0032x over previous
#include <cuda_runtime.h>
#include <cstdint>

#define NB      16384
#define DTC     0.1f
#define FPB     32
#define THREADS 128
#define FS      833              // filter stride (words), odd -> conflict-free STS
#define RSTEP   52               // row stride: 52 step slots (max half size)
#define SMEM_WORDS (32 * FS)     // 26656
#define SMEM_BYTES (SMEM_WORDS * 4)   // 106624 B -> 2 blocks/SM

__constant__ int ROWMAP[22] = {0,1,2,3,4,5,
                               6,7,8,9, 7,10,11,12, 8,11,13,14, 9,12,14,15};

struct St  { float x0,x1,x2,x3,p00,p01,p02,p03,p11,p12,p13,p22,p23,p33; };
struct Cst { float q00,q01,q02,q03,q11,q12,q13,q22,q23,q33,r00,r01,r11; };

// one exact-collapsed UKF step (affine motion => linear KF);
// Pn via K*A_c^T (== K S K^T since K = A_c S^{-1}); stages 16 unique rows.
__device__ __forceinline__ void ukf_step(
    St& s, const Cst& c, float z0, float z1, float ux, float uy,
    float* __restrict__ stage_f, int sp)
{
    const float xp0 = s.x0 + DTC * s.x2 + 0.5f * DTC * DTC * ux;
    const float xp1 = s.x1 + DTC * s.x3 + 0.5f * DTC * DTC * uy;
    const float xp2 = s.x2 + DTC * ux;
    const float xp3 = s.x3 + DTC * uy;

    const float a02 = s.p02 + DTC * s.p22;
    const float a03 = s.p03 + DTC * s.p23;
    const float a12 = s.p12 + DTC * s.p23;
    const float a13 = s.p13 + DTC * s.p33;
    const float a00 = s.p00 + DTC * s.p02 + DTC * a02;
    const float a11 = s.p11 + DTC * s.p13 + DTC * a13;
    const float a01 = s.p01 + DTC * s.p03 + DTC * a12;

    const float s00 = a00 + c.r00;
    const float s01 = a01 + c.r01;
    const float s11 = a11 + c.r11;
    const float idet = __fdividef(1.0f, s00 * s11 - s01 * s01);
    const float i00 =  s11 * idet;
    const float i01 = -s01 * idet;
    const float i11 =  s00 * idet;

    const float K00 = a00 * i00 + a01 * i01, K01 = a00 * i01 + a01 * i11;
    const float K10 = a01 * i00 + a11 * i01, K11 = a01 * i01 + a11 * i11;
    const float K20 = a02 * i00 + a12 * i01, K21 = a02 * i01 + a12 * i11;
    const float K30 = a03 * i00 + a13 * i01, K31 = a03 * i01 + a13 * i11;

    const float in0 = z0 - xp0, in1 = z1 - xp1;
    const float xn0 = xp0 + K00 * in0 + K01 * in1;
    const float xn1 = xp1 + K10 * in0 + K11 * in1;
    const float xn2 = xp2 + K20 * in0 + K21 * in1;
    const float xn3 = xp3 + K30 * in0 + K31 * in1;

    s.p00 = (a00 + c.q00) - (K00 * a00 + K01 * a01);
    s.p01 = (a01 + c.q01) - (K00 * a01 + K01 * a11);
    s.p02 = (a02 + c.q02) - (K00 * a02 + K01 * a12);
    s.p03 = (a03 + c.q03) - (K00 * a03 + K01 * a13);
    s.p11 = (a11 + c.q11) - (K10 * a01 + K11 * a11);
    s.p12 = (a12 + c.q12) - (K10 * a02 + K11 * a12);
    s.p13 = (a13 + c.q13) - (K10 * a03 + K11 * a13);
    s.p22 = (s.p22 + c.q22) - (K20 * a02 + K21 * a12);
    s.p23 = (s.p23 + c.q23) - (K20 * a03 + K21 * a13);
    s.p33 = (s.p33 + c.q33) - (K30 * a03 + K31 * a13);
    s.x0 = xn0; s.x1 = xn1; s.x2 = xn2; s.x3 = xn3;

    stage_f[ 0 * RSTEP + sp] = xp0;   stage_f[ 1 * RSTEP + sp] = xp1;
    stage_f[ 2 * RSTEP + sp] = xn0;   stage_f[ 3 * RSTEP + sp] = xn1;
    stage_f[ 4 * RSTEP + sp] = xn2;   stage_f[ 5 * RSTEP + sp] = xn3;
    stage_f[ 6 * RSTEP + sp] = s.p00; stage_f[ 7 * RSTEP + sp] = s.p01;
    stage_f[ 8 * RSTEP + sp] = s.p02; stage_f[ 9 * RSTEP + sp] = s.p03;
    stage_f[10 * RSTEP + sp] = s.p11; stage_f[11 * RSTEP + sp] = s.p12;
    stage_f[12 * RSTEP + sp] = s.p13; stage_f[13 * RSTEP + sp] = s.p22;
    stage_f[14 * RSTEP + sp] = s.p23; stage_f[15 * RSTEP + sp] = s.p33;
}

// run one 8-step chunk from prefetched registers
__device__ __forceinline__ void run_chunk8(
    St& s, const Cst& c, float* __restrict__ stage_f, int slot0,
    float4 z0a, float4 z0b, float4 z1a, float4 z1b,
    float4 c0, float4 c1, float4 c2, float4 c3)
{
    const float z0s[8] = {z0a.x,z0a.y,z0a.z,z0a.w, z0b.x,z0b.y,z0b.z,z0b.w};
    const float z1s[8] = {z1a.x,z1a.y,z1a.z,z1a.w, z1b.x,z1b.y,z1b.z,z1b.w};
    const float uxs[8] = {c0.x,c0.z,c1.x,c1.z, c2.x,c2.z,c3.x,c3.z};
    const float uys[8] = {c0.y,c0.w,c1.y,c1.w, c2.y,c2.w,c3.y,c3.w};
#pragma unroll
    for (int sp = 0; sp < 8; sp++)
        ukf_step(s, c, z0s[sp], z1s[sp], uxs[sp], uys[sp], stage_f, slot0 + sp);
}

// flush one half: G float4-groups per output row, global step base sglob
template <int G, int NIT>
__device__ __forceinline__ void flush_half(
    const float* __restrict__ sm, float* __restrict__ preds,
    float* __restrict__ states, float* __restrict__ covs,
    int b0, int tid, int sglob)
{
    const int TOT = 32 * 22 * G;
#pragma unroll 1
    for (int k = 0; k < NIT; k++) {
        const int id = tid + THREADS * k;
        if (TOT % THREADS != 0) { if (id >= TOT) break; }
        const int f   = id / (22 * G);
        const int rem = id % (22 * G);
        const int R   = rem / G;
        const int g   = rem % G;
        const float* src = sm + f * FS + ROWMAP[R] * RSTEP + 4 * g;
        float4 v = make_float4(src[0], src[1], src[2], src[3]);
        const int gb = b0 + f;
        float* dst = (R < 2) ? preds  + (size_t)gb * 200  + R * 100
                   : (R < 6) ? states + (size_t)gb * 400  + (R - 2) * 100
                             : covs   + (size_t)gb * 1600 + (R - 6) * 100;
        *reinterpret_cast<float4*>(dst + sglob + 4 * g) = v;
    }
}

__global__ __launch_bounds__(THREADS, 1) void ukf_kernel(
    const float* __restrict__ meas, const float* __restrict__ state0,
    const float* __restrict__ cov0, const float* __restrict__ ctrl,
    const float* __restrict__ Qm,   const float* __restrict__ Rm,
    float* __restrict__ preds, float* __restrict__ states, float* __restrict__ covs)
{
    extern __shared__ float sm[];
    const int tid = threadIdx.x;
    const int b0  = blockIdx.x * FPB;

    St s;  Cst c;
    const float* mrow = nullptr;
    const float* crow = nullptr;
    float* stage_f = nullptr;
    float4 pz0a, pz0b, pz1a, pz1b, pc0, pc1, pc2, pc3;

    if (tid < 32) {
        const int b = b0 + tid;
        float4 xv = *reinterpret_cast<const float4*>(state0 + (size_t)b * 4);
        s.x0 = xv.x; s.x1 = xv.y; s.x2 = xv.z; s.x3 = xv.w;
        const float4* pv = reinterpret_cast<const float4*>(cov0 + (size_t)b * 16);
        float4 r0 = pv[0], r1 = pv[1], r2 = pv[2], r3 = pv[3];
        s.p00 = r0.x; s.p01 = r0.y; s.p02 = r0.z; s.p03 = r0.w;
        s.p11 = r1.y; s.p12 = r1.z; s.p13 = r1.w;
        s.p22 = r2.z; s.p23 = r2.w; s.p33 = r3.w;

        c.q00 = Qm[0];  c.q01 = Qm[1];  c.q02 = Qm[2];  c.q03 = Qm[3];
        c.q11 = Qm[5];  c.q12 = Qm[6];  c.q13 = Qm[7];
        c.q22 = Qm[10]; c.q23 = Qm[11]; c.q33 = Qm[15];
        c.r00 = Rm[0];  c.r01 = Rm[1];  c.r11 = Rm[3];

        mrow = meas + (size_t)b * 200;
        crow = ctrl + (size_t)b * 200;
        stage_f = sm + tid * FS;

        // prefetch chunk 0
        pz0a = *reinterpret_cast<const float4*>(mrow);
        pz0b = *reinterpret_cast<const float4*>(mrow + 4);
        pz1a = *reinterpret_cast<const float4*>(mrow + 100);
        pz1b = *reinterpret_cast<const float4*>(mrow + 104);
        pc0  = *reinterpret_cast<const float4*>(crow);
        pc1  = *reinterpret_cast<const float4*>(crow + 4);
        pc2  = *reinterpret_cast<const float4*>(crow + 8);
        pc3  = *reinterpret_cast<const float4*>(crow + 12);

        // ---- H1: chunks 0..5 (steps 0..47), slots 0..47 ----
#pragma unroll 1
        for (int ch = 0; ch < 6; ch++) {
            float4 z0a = pz0a, z0b = pz0b, z1a = pz1a, z1b = pz1b;
            float4 c0 = pc0, c1 = pc1, c2 = pc2, c3 = pc3;
            const int s0n = (ch + 1) * 8;     // 8..48, all full chunks valid
            pz0a = *reinterpret_cast<const float4*>(mrow + s0n);
            pz0b = *reinterpret_cast<const float4*>(mrow + s0n + 4);
            pz1a = *reinterpret_cast<const float4*>(mrow + 100 + s0n);
            pz1b = *reinterpret_cast<const float4*>(mrow + 104 + s0n);
            pc0  = *reinterpret_cast<const float4*>(crow + 2 * s0n);
            pc1  = *reinterpret_cast<const float4*>(crow + 2 * s0n + 4);
            pc2  = *reinterpret_cast<const float4*>(crow + 2 * s0n + 8);
            pc3  = *reinterpret_cast<const float4*>(crow + 2 * s0n + 12);
            run_chunk8(s, c, stage_f, ch * 8, z0a, z0b, z1a, z1b, c0, c1, c2, c3);
        }
    }

    __syncthreads();                         // H1 staging complete
    flush_half<12, 66>(sm, preds, states, covs, b0, tid, 0);
    __syncthreads();                         // staging reusable

    if (tid < 32) {
        // ---- H2: chunks 6..11 (steps 48..95), slots 0..47; tail 96..99 slots 48..51 ----
#pragma unroll 1
        for (int ch = 6; ch < 12; ch++) {
            float4 z0a = pz0a, z0b = pz0b, z1a = pz1a, z1b = pz1b;
            float4 c0 = pc0, c1 = pc1, c2 = pc2, c3 = pc3;
            if (ch < 11) {
                const int s0n = (ch + 1) * 8;
                pz0a = *reinterpret_cast<const float4*>(mrow + s0n);
                pz0b = *reinterpret_cast<const float4*>(mrow + s0n + 4);
                pz1a = *reinterpret_cast<const float4*>(mrow + 100 + s0n);
                pz1b = *reinterpret_cast<const float4*>(mrow + 104 + s0n);
                pc0  = *reinterpret_cast<const float4*>(crow + 2 * s0n);
                pc1  = *reinterpret_cast<const float4*>(crow + 2 * s0n + 4);
                pc2  = *reinterpret_cast<const float4*>(crow + 2 * s0n + 8);
                pc3  = *reinterpret_cast<const float4*>(crow + 2 * s0n + 12);
            } else {
                // tail prefetch (4 steps at s0=96): only in-bounds pieces
                pz0a = *reinterpret_cast<const float4*>(mrow + 96);
                pz1a = *reinterpret_cast<const float4*>(mrow + 196);
                pc0  = *reinterpret_cast<const float4*>(crow + 192);
                pc1  = *reinterpret_cast<const float4*>(crow + 196);
            }
            run_chunk8(s, c, stage_f, (ch - 6) * 8, z0a, z0b, z1a, z1b, c0, c1, c2, c3);
        }
        // tail: 4 steps, slots 48..51
        {
            const float z0s[4] = {pz0a.x, pz0a.y, pz0a.z, pz0a.w};
            const float z1s[4] = {pz1a.x, pz1a.y, pz1a.z, pz1a.w};
            const float uxs[4] = {pc0.x, pc0.z, pc1.x, pc1.z};
            const float uys[4] = {pc0.y, pc0.w, pc1.y, pc1.w};
#pragma unroll
            for (int sp = 0; sp < 4; sp++)
                ukf_step(s, c, z0s[sp], z1s[sp], uxs[sp], uys[sp],
                         stage_f, 48 + sp);
        }
    }

    __syncthreads();                         // H2 staging complete
    flush_half<13, 72>(sm, preds, states, covs, b0, tid, 48);
}

extern "C" void kernel_launch(void* const* d_in, const int* in_sizes, int n_in,
                              void* d_out, int out_size)
{
    const float* meas  = (const float*)d_in[0];
    const float* state = (const float*)d_in[1];
    const float* cov   = (const float*)d_in[2];
    const float* ctrl  = (const float*)d_in[3];
    const float* Q     = (const float*)d_in[4];
    const float* R     = (const float*)d_in[5];

    float* out    = (float*)d_out;
    float* preds  = out;                         // 16384*2*100
    float* states = preds  + (size_t)NB * 200;   // 16384*4*100
    float* covs   = states + (size_t)NB * 400;   // 16384*16*100

    static int smem_set = 0;
    if (!smem_set) {
        cudaFuncSetAttribute(ukf_kernel,
                             cudaFuncAttributeMaxDynamicSharedMemorySize, SMEM_BYTES);
        smem_set = 1;
    }

    ukf_kernel<<<NB / FPB, THREADS, SMEM_BYTES>>>(meas, state, cov, ctrl, Q, R,
                                                  preds, states, covs);
}

// round 11
// speedup vs baseline: 1.0466x; 1.0433x over previous
#include <cuda_runtime.h>
#include <cstdint>

#define NB      16384
#define DTC     0.1f
#define FPB     32
#define THREADS 128
#define FS      836              // filter stride (words): %4==0 (LDS/STS.128 align),
                                 // FS/4=209 odd -> conflict-free 128-bit phases
#define RSTEP   52               // step slots per row (max half = 52)
#define SMEM_WORDS (32 * FS)     // 26752
#define SMEM_BYTES (SMEM_WORDS * 4)   // 107008 B -> 2 blocks/SM

__constant__ int ROWMAP[22] = {0,1,2,3,4,5,
                               6,7,8,9, 7,10,11,12, 8,11,13,14, 9,12,14,15};

struct St  { float x0,x1,x2,x3,p00,p01,p02,p03,p11,p12,p13,p22,p23,p33; };
struct Cst { float q00,q01,q02,q03,q11,q12,q13,q22,q23,q33,r00,r01,r11; };

// one exact-collapsed UKF step (affine motion => linear KF);
// Pn via K*A_c^T (== K S K^T since K = A_c S^{-1}); outputs into buf[.][j]
__device__ __forceinline__ void ukf_step(
    St& s, const Cst& c, float z0, float z1, float ux, float uy,
    float (&buf)[16][4], int j)
{
    const float xp0 = s.x0 + DTC * s.x2 + 0.5f * DTC * DTC * ux;
    const float xp1 = s.x1 + DTC * s.x3 + 0.5f * DTC * DTC * uy;
    const float xp2 = s.x2 + DTC * ux;
    const float xp3 = s.x3 + DTC * uy;

    const float a02 = s.p02 + DTC * s.p22;
    const float a03 = s.p03 + DTC * s.p23;
    const float a12 = s.p12 + DTC * s.p23;
    const float a13 = s.p13 + DTC * s.p33;
    const float a00 = s.p00 + DTC * s.p02 + DTC * a02;
    const float a11 = s.p11 + DTC * s.p13 + DTC * a13;
    const float a01 = s.p01 + DTC * s.p03 + DTC * a12;

    const float s00 = a00 + c.r00;
    const float s01 = a01 + c.r01;
    const float s11 = a11 + c.r11;
    const float idet = __fdividef(1.0f, s00 * s11 - s01 * s01);
    const float i00 =  s11 * idet;
    const float i01 = -s01 * idet;
    const float i11 =  s00 * idet;

    const float K00 = a00 * i00 + a01 * i01, K01 = a00 * i01 + a01 * i11;
    const float K10 = a01 * i00 + a11 * i01, K11 = a01 * i01 + a11 * i11;
    const float K20 = a02 * i00 + a12 * i01, K21 = a02 * i01 + a12 * i11;
    const float K30 = a03 * i00 + a13 * i01, K31 = a03 * i01 + a13 * i11;

    const float in0 = z0 - xp0, in1 = z1 - xp1;
    const float xn0 = xp0 + K00 * in0 + K01 * in1;
    const float xn1 = xp1 + K10 * in0 + K11 * in1;
    const float xn2 = xp2 + K20 * in0 + K21 * in1;
    const float xn3 = xp3 + K30 * in0 + K31 * in1;

    s.p00 = (a00 + c.q00) - (K00 * a00 + K01 * a01);
    s.p01 = (a01 + c.q01) - (K00 * a01 + K01 * a11);
    s.p02 = (a02 + c.q02) - (K00 * a02 + K01 * a12);
    s.p03 = (a03 + c.q03) - (K00 * a03 + K01 * a13);
    s.p11 = (a11 + c.q11) - (K10 * a01 + K11 * a11);
    s.p12 = (a12 + c.q12) - (K10 * a02 + K11 * a12);
    s.p13 = (a13 + c.q13) - (K10 * a03 + K11 * a13);
    s.p22 = (s.p22 + c.q22) - (K20 * a02 + K21 * a12);
    s.p23 = (s.p23 + c.q23) - (K20 * a03 + K21 * a13);
    s.p33 = (s.p33 + c.q33) - (K30 * a03 + K31 * a13);
    s.x0 = xn0; s.x1 = xn1; s.x2 = xn2; s.x3 = xn3;

    buf[0][j]  = xp0;   buf[1][j]  = xp1;
    buf[2][j]  = xn0;   buf[3][j]  = xn1;
    buf[4][j]  = xn2;   buf[5][j]  = xn3;
    buf[6][j]  = s.p00; buf[7][j]  = s.p01;
    buf[8][j]  = s.p02; buf[9][j]  = s.p03;
    buf[10][j] = s.p11; buf[11][j] = s.p12;
    buf[12][j] = s.p13; buf[13][j] = s.p22;
    buf[14][j] = s.p23; buf[15][j] = s.p33;
}

// 4 steps -> 16 STS.128 (conflict-free phases: 209f mod 8 distinct)
__device__ __forceinline__ void stage4(
    float* __restrict__ stage_f, int slot, const float (&buf)[16][4])
{
#pragma unroll
    for (int r = 0; r < 16; r++)
        *reinterpret_cast<float4*>(stage_f + r * RSTEP + slot) =
            make_float4(buf[r][0], buf[r][1], buf[r][2], buf[r][3]);
}

// 8 steps from prefetched registers: two 4-step groups
__device__ __forceinline__ void run_chunk8(
    St& s, const Cst& c, float* __restrict__ stage_f, int slot0,
    float4 z0a, float4 z0b, float4 z1a, float4 z1b,
    float4 c0, float4 c1, float4 c2, float4 c3)
{
    float buf[16][4];
    ukf_step(s, c, z0a.x, z1a.x, c0.x, c0.y, buf, 0);
    ukf_step(s, c, z0a.y, z1a.y, c0.z, c0.w, buf, 1);
    ukf_step(s, c, z0a.z, z1a.z, c1.x, c1.y, buf, 2);
    ukf_step(s, c, z0a.w, z1a.w, c1.z, c1.w, buf, 3);
    stage4(stage_f, slot0, buf);
    ukf_step(s, c, z0b.x, z1b.x, c2.x, c2.y, buf, 0);
    ukf_step(s, c, z0b.y, z1b.y, c2.z, c2.w, buf, 1);
    ukf_step(s, c, z0b.z, z1b.z, c3.x, c3.y, buf, 2);
    ukf_step(s, c, z0b.w, z1b.w, c3.z, c3.w, buf, 3);
    stage4(stage_f, slot0 + 4, buf);
}

// flush one half: G float4-groups per output row, global step base sglob
template <int G, int NIT>
__device__ __forceinline__ void flush_half(
    const float* __restrict__ sm, float* __restrict__ preds,
    float* __restrict__ states, float* __restrict__ covs,
    int b0, int tid, int sglob)
{
    const int TOT = 32 * 22 * G;
#pragma unroll 1
    for (int k = 0; k < NIT; k++) {
        const int id = tid + THREADS * k;
        if (TOT % THREADS != 0) { if (id >= TOT) break; }
        const int f   = id / (22 * G);
        const int rem = id % (22 * G);
        const int R   = rem / G;
        const int g   = rem % G;
        float4 v = *reinterpret_cast<const float4*>(
            sm + f * FS + ROWMAP[R] * RSTEP + 4 * g);
        const int gb = b0 + f;
        float* dst = (R < 2) ? preds  + (size_t)gb * 200  + R * 100
                   : (R < 6) ? states + (size_t)gb * 400  + (R - 2) * 100
                             : covs   + (size_t)gb * 1600 + (R - 6) * 100;
        *reinterpret_cast<float4*>(dst + sglob + 4 * g) = v;
    }
}

__global__ __launch_bounds__(THREADS, 1) void ukf_kernel(
    const float* __restrict__ meas, const float* __restrict__ state0,
    const float* __restrict__ cov0, const float* __restrict__ ctrl,
    const float* __restrict__ Qm,   const float* __restrict__ Rm,
    float* __restrict__ preds, float* __restrict__ states, float* __restrict__ covs)
{
    extern __shared__ float sm[];
    const int tid = threadIdx.x;
    const int bid = blockIdx.x;
    const int b0  = bid * FPB;
    // rotate compute warp so co-resident blocks (bid, bid+~148) use different SMSPs
    const int cw  = ((bid >> 2) + bid) & 3;
    const bool comp = (tid >> 5) == cw;
    const int lane = tid & 31;

    St s;  Cst c;
    const float* mrow = nullptr;
    const float* crow = nullptr;
    float* stage_f = nullptr;
    float4 pz0a, pz0b, pz1a, pz1b, pc0, pc1, pc2, pc3;

    if (comp) {
        const int b = b0 + lane;
        float4 xv = *reinterpret_cast<const float4*>(state0 + (size_t)b * 4);
        s.x0 = xv.x; s.x1 = xv.y; s.x2 = xv.z; s.x3 = xv.w;
        const float4* pv = reinterpret_cast<const float4*>(cov0 + (size_t)b * 16);
        float4 r0 = pv[0], r1 = pv[1], r2 = pv[2], r3 = pv[3];
        s.p00 = r0.x; s.p01 = r0.y; s.p02 = r0.z; s.p03 = r0.w;
        s.p11 = r1.y; s.p12 = r1.z; s.p13 = r1.w;
        s.p22 = r2.z; s.p23 = r2.w; s.p33 = r3.w;

        c.q00 = Qm[0];  c.q01 = Qm[1];  c.q02 = Qm[2];  c.q03 = Qm[3];
        c.q11 = Qm[5];  c.q12 = Qm[6];  c.q13 = Qm[7];
        c.q22 = Qm[10]; c.q23 = Qm[11]; c.q33 = Qm[15];
        c.r00 = Rm[0];  c.r01 = Rm[1];  c.r11 = Rm[3];

        mrow = meas + (size_t)b * 200;
        crow = ctrl + (size_t)b * 200;
        stage_f = sm + lane * FS;

        pz0a = *reinterpret_cast<const float4*>(mrow);
        pz0b = *reinterpret_cast<const float4*>(mrow + 4);
        pz1a = *reinterpret_cast<const float4*>(mrow + 100);
        pz1b = *reinterpret_cast<const float4*>(mrow + 104);
        pc0  = *reinterpret_cast<const float4*>(crow);
        pc1  = *reinterpret_cast<const float4*>(crow + 4);
        pc2  = *reinterpret_cast<const float4*>(crow + 8);
        pc3  = *reinterpret_cast<const float4*>(crow + 12);

        // ---- H1: chunks 0..5 (steps 0..47) -> slots 0..47 ----
#pragma unroll 1
        for (int ch = 0; ch < 6; ch++) {
            float4 z0a = pz0a, z0b = pz0b, z1a = pz1a, z1b = pz1b;
            float4 c0 = pc0, c1 = pc1, c2 = pc2, c3 = pc3;
            const int s0n = (ch + 1) * 8;
            pz0a = *reinterpret_cast<const float4*>(mrow + s0n);
            pz0b = *reinterpret_cast<const float4*>(mrow + s0n + 4);
            pz1a = *reinterpret_cast<const float4*>(mrow + 100 + s0n);
            pz1b = *reinterpret_cast<const float4*>(mrow + 104 + s0n);
            pc0  = *reinterpret_cast<const float4*>(crow + 2 * s0n);
            pc1  = *reinterpret_cast<const float4*>(crow + 2 * s0n + 4);
            pc2  = *reinterpret_cast<const float4*>(crow + 2 * s0n + 8);
            pc3  = *reinterpret_cast<const float4*>(crow + 2 * s0n + 12);
            run_chunk8(s, c, stage_f, ch * 8, z0a, z0b, z1a, z1b, c0, c1, c2, c3);
        }
    }

    __syncthreads();                          // H1 staging complete
    flush_half<12, 66>(sm, preds, states, covs, b0, tid, 0);
    __syncthreads();                          // staging reusable

    if (comp) {
        // ---- H2: chunks 6..11 (steps 48..95) -> slots 0..47; tail -> 48..51 ----
#pragma unroll 1
        for (int ch = 6; ch < 12; ch++) {
            float4 z0a = pz0a, z0b = pz0b, z1a = pz1a, z1b = pz1b;
            float4 c0 = pc0, c1 = pc1, c2 = pc2, c3 = pc3;
            if (ch < 11) {
                const int s0n = (ch + 1) * 8;
                pz0a = *reinterpret_cast<const float4*>(mrow + s0n);
                pz0b = *reinterpret_cast<const float4*>(mrow + s0n + 4);
                pz1a = *reinterpret_cast<const float4*>(mrow + 100 + s0n);
                pz1b = *reinterpret_cast<const float4*>(mrow + 104 + s0n);
                pc0  = *reinterpret_cast<const float4*>(crow + 2 * s0n);
                pc1  = *reinterpret_cast<const float4*>(crow + 2 * s0n + 4);
                pc2  = *reinterpret_cast<const float4*>(crow + 2 * s0n + 8);
                pc3  = *reinterpret_cast<const float4*>(crow + 2 * s0n + 12);
            } else {
                pz0a = *reinterpret_cast<const float4*>(mrow + 96);
                pz1a = *reinterpret_cast<const float4*>(mrow + 196);
                pc0  = *reinterpret_cast<const float4*>(crow + 192);
                pc1  = *reinterpret_cast<const float4*>(crow + 196);
            }
            run_chunk8(s, c, stage_f, (ch - 6) * 8, z0a, z0b, z1a, z1b, c0, c1, c2, c3);
        }
        // tail: 4 steps -> slot 48
        {
            float buf[16][4];
            ukf_step(s, c, pz0a.x, pz1a.x, pc0.x, pc0.y, buf, 0);
            ukf_step(s, c, pz0a.y, pz1a.y, pc0.z, pc0.w, buf, 1);
            ukf_step(s, c, pz0a.z, pz1a.z, pc1.x, pc1.y, buf, 2);
            ukf_step(s, c, pz0a.w, pz1a.w, pc1.z, pc1.w, buf, 3);
            stage4(stage_f, 48, buf);
        }
    }

    __syncthreads();                          // H2 staging complete
    flush_half<13, 72>(sm, preds, states, covs, b0, tid, 48);
}

extern "C" void kernel_launch(void* const* d_in, const int* in_sizes, int n_in,
                              void* d_out, int out_size)
{
    const float* meas  = (const float*)d_in[0];
    const float* state = (const float*)d_in[1];
    const float* cov   = (const float*)d_in[2];
    const float* ctrl  = (const float*)d_in[3];
    const float* Q     = (const float*)d_in[4];
    const float* R     = (const float*)d_in[5];

    float* out    = (float*)d_out;
    float* preds  = out;                         // 16384*2*100
    float* states = preds  + (size_t)NB * 200;   // 16384*4*100
    float* covs   = states + (size_t)NB * 400;   // 16384*16*100

    static int smem_set = 0;
    if (!smem_set) {
        cudaFuncSetAttribute(ukf_kernel,
                             cudaFuncAttributeMaxDynamicSharedMemorySize, SMEM_BYTES);
        smem_set = 1;
    }

    ukf_kernel<<<NB / FPB, THREADS, SMEM_BYTES>>>(meas, state, cov, ctrl, Q, R,
                                                  preds, states, covs);
}

// round 12
// speedup vs baseline: 1.0945x; 1.0457x over previous
#include <cuda_runtime.h>
#include <cstdint>

#define NB      16384
#define DTC     0.1f
#define FPB     32
#define THREADS 128
#define FS      836              // filter stride (words): %4==0, FS/4=209 odd ->
                                 // conflict-free 128-bit smem phases
#define RSTEP   52               // step slots per row (max half = 52)
#define SMEM_WORDS (32 * FS)     // 26752
#define SMEM_BYTES (SMEM_WORDS * 4)   // 107008 B -> 2 blocks/SM

struct St  { float x0,x1,x2,x3,p00,p01,p02,p03,p11,p12,p13,p22,p23,p33; };
struct Cst { float q00,q01,q02,q03,q11,q12,q13,q22,q23,q33,r00,r01,r11; };

// one exact-collapsed UKF step (affine motion => linear KF);
// Pn via K*A_c^T (== K S K^T since K = A_c S^{-1}); outputs into buf[.][j]
__device__ __forceinline__ void ukf_step(
    St& s, const Cst& c, float z0, float z1, float ux, float uy,
    float (&buf)[16][4], int j)
{
    const float xp0 = s.x0 + DTC * s.x2 + 0.5f * DTC * DTC * ux;
    const float xp1 = s.x1 + DTC * s.x3 + 0.5f * DTC * DTC * uy;
    const float xp2 = s.x2 + DTC * ux;
    const float xp3 = s.x3 + DTC * uy;

    const float a02 = s.p02 + DTC * s.p22;
    const float a03 = s.p03 + DTC * s.p23;
    const float a12 = s.p12 + DTC * s.p23;
    const float a13 = s.p13 + DTC * s.p33;
    const float a00 = s.p00 + DTC * s.p02 + DTC * a02;
    const float a11 = s.p11 + DTC * s.p13 + DTC * a13;
    const float a01 = s.p01 + DTC * s.p03 + DTC * a12;

    const float s00 = a00 + c.r00;
    const float s01 = a01 + c.r01;
    const float s11 = a11 + c.r11;
    const float idet = __fdividef(1.0f, s00 * s11 - s01 * s01);
    const float i00 =  s11 * idet;
    const float i01 = -s01 * idet;
    const float i11 =  s00 * idet;

    const float K00 = a00 * i00 + a01 * i01, K01 = a00 * i01 + a01 * i11;
    const float K10 = a01 * i00 + a11 * i01, K11 = a01 * i01 + a11 * i11;
    const float K20 = a02 * i00 + a12 * i01, K21 = a02 * i01 + a12 * i11;
    const float K30 = a03 * i00 + a13 * i01, K31 = a03 * i01 + a13 * i11;

    const float in0 = z0 - xp0, in1 = z1 - xp1;
    const float xn0 = xp0 + K00 * in0 + K01 * in1;
    const float xn1 = xp1 + K10 * in0 + K11 * in1;
    const float xn2 = xp2 + K20 * in0 + K21 * in1;
    const float xn3 = xp3 + K30 * in0 + K31 * in1;

    s.p00 = (a00 + c.q00) - (K00 * a00 + K01 * a01);
    s.p01 = (a01 + c.q01) - (K00 * a01 + K01 * a11);
    s.p02 = (a02 + c.q02) - (K00 * a02 + K01 * a12);
    s.p03 = (a03 + c.q03) - (K00 * a03 + K01 * a13);
    s.p11 = (a11 + c.q11) - (K10 * a01 + K11 * a11);
    s.p12 = (a12 + c.q12) - (K10 * a02 + K11 * a12);
    s.p13 = (a13 + c.q13) - (K10 * a03 + K11 * a13);
    s.p22 = (s.p22 + c.q22) - (K20 * a02 + K21 * a12);
    s.p23 = (s.p23 + c.q23) - (K20 * a03 + K21 * a13);
    s.p33 = (s.p33 + c.q33) - (K30 * a03 + K31 * a13);
    s.x0 = xn0; s.x1 = xn1; s.x2 = xn2; s.x3 = xn3;

    buf[0][j]  = xp0;   buf[1][j]  = xp1;
    buf[2][j]  = xn0;   buf[3][j]  = xn1;
    buf[4][j]  = xn2;   buf[5][j]  = xn3;
    buf[6][j]  = s.p00; buf[7][j]  = s.p01;
    buf[8][j]  = s.p02; buf[9][j]  = s.p03;
    buf[10][j] = s.p11; buf[11][j] = s.p12;
    buf[12][j] = s.p13; buf[13][j] = s.p22;
    buf[14][j] = s.p23; buf[15][j] = s.p33;
}

// 4 steps -> 16 STS.128
__device__ __forceinline__ void stage4(
    float* __restrict__ stage_f, int slot, const float (&buf)[16][4])
{
#pragma unroll
    for (int r = 0; r < 16; r++)
        *reinterpret_cast<float4*>(stage_f + r * RSTEP + slot) =
            make_float4(buf[r][0], buf[r][1], buf[r][2], buf[r][3]);
}

// 8 steps from prefetched registers
__device__ __forceinline__ void run_chunk8(
    St& s, const Cst& c, float* __restrict__ stage_f, int slot0,
    float4 z0a, float4 z0b, float4 z1a, float4 z1b,
    float4 c0, float4 c1, float4 c2, float4 c3)
{
    float buf[16][4];
    ukf_step(s, c, z0a.x, z1a.x, c0.x, c0.y, buf, 0);
    ukf_step(s, c, z0a.y, z1a.y, c0.z, c0.w, buf, 1);
    ukf_step(s, c, z0a.z, z1a.z, c1.x, c1.y, buf, 2);
    ukf_step(s, c, z0a.w, z1a.w, c1.z, c1.w, buf, 3);
    stage4(stage_f, slot0, buf);
    ukf_step(s, c, z0b.x, z1b.x, c2.x, c2.y, buf, 0);
    ukf_step(s, c, z0b.y, z1b.y, c2.z, c2.w, buf, 1);
    ukf_step(s, c, z0b.z, z1b.z, c3.x, c3.y, buf, 2);
    ukf_step(s, c, z0b.w, z1b.w, c3.z, c3.w, buf, 3);
    stage4(stage_f, slot0 + 4, buf);
}

// division-free dense flush: thread owns (f = tid>>2, h = tid&3);
// fully-unrolled R loop with constexpr row map -> pure shift/add addressing.
template <int G>
__device__ __forceinline__ void flush_half(
    const float* __restrict__ src_f, float* __restrict__ pp,
    float* __restrict__ ps, float* __restrict__ pc, int h, int sglob)
{
    constexpr int MAP[22] = {0,1,2,3,4,5,
                             6,7,8,9, 7,10,11,12, 8,11,13,14, 9,12,14,15};
#pragma unroll
    for (int R = 0; R < 22; R++) {
        const float* src = src_f + MAP[R] * RSTEP;
        float* dst = (R < 2) ? pp + R * 100
                   : (R < 6) ? ps + (R - 2) * 100
                             : pc + (R - 6) * 100;
#pragma unroll
        for (int kk = 0; kk < (G + 3) / 4; kk++) {
            const int g = h + 4 * kk;
            if ((G & 3) == 0 || g < G) {
                float4 v = *reinterpret_cast<const float4*>(src + 4 * g);
                *reinterpret_cast<float4*>(dst + sglob + 4 * g) = v;
            }
        }
    }
}

__global__ __launch_bounds__(THREADS, 1) void ukf_kernel(
    const float* __restrict__ meas, const float* __restrict__ state0,
    const float* __restrict__ cov0, const float* __restrict__ ctrl,
    const float* __restrict__ Qm,   const float* __restrict__ Rm,
    float* __restrict__ preds, float* __restrict__ states, float* __restrict__ covs)
{
    extern __shared__ float sm[];
    const int tid = threadIdx.x;
    const int bid = blockIdx.x;
    const int b0  = bid * FPB;
    // rotate compute warp so co-resident blocks use different SMSPs
    const int cw  = ((bid >> 2) + bid) & 3;
    const bool comp = (tid >> 5) == cw;
    const int lane = tid & 31;

    // flush mapping (all threads)
    const int ff = tid >> 2, fh = tid & 3;
    const float* fsrc = sm + ff * FS;
    float* fpp = preds  + (size_t)(b0 + ff) * 200;
    float* fps = states + (size_t)(b0 + ff) * 400;
    float* fpc = covs   + (size_t)(b0 + ff) * 1600;

    St s;  Cst c;
    const float* mrow = nullptr;
    const float* crow = nullptr;
    float* stage_f = nullptr;
    float4 pz0a, pz0b, pz1a, pz1b, pc0, pc1, pc2, pc3;

    if (comp) {
        const int b = b0 + lane;
        float4 xv = *reinterpret_cast<const float4*>(state0 + (size_t)b * 4);
        s.x0 = xv.x; s.x1 = xv.y; s.x2 = xv.z; s.x3 = xv.w;
        const float4* pv = reinterpret_cast<const float4*>(cov0 + (size_t)b * 16);
        float4 r0 = pv[0], r1 = pv[1], r2 = pv[2], r3 = pv[3];
        s.p00 = r0.x; s.p01 = r0.y; s.p02 = r0.z; s.p03 = r0.w;
        s.p11 = r1.y; s.p12 = r1.z; s.p13 = r1.w;
        s.p22 = r2.z; s.p23 = r2.w; s.p33 = r3.w;

        c.q00 = Qm[0];  c.q01 = Qm[1];  c.q02 = Qm[2];  c.q03 = Qm[3];
        c.q11 = Qm[5];  c.q12 = Qm[6];  c.q13 = Qm[7];
        c.q22 = Qm[10]; c.q23 = Qm[11]; c.q33 = Qm[15];
        c.r00 = Rm[0];  c.r01 = Rm[1];  c.r11 = Rm[3];

        mrow = meas + (size_t)b * 200;
        crow = ctrl + (size_t)b * 200;
        stage_f = sm + lane * FS;

        pz0a = *reinterpret_cast<const float4*>(mrow);
        pz0b = *reinterpret_cast<const float4*>(mrow + 4);
        pz1a = *reinterpret_cast<const float4*>(mrow + 100);
        pz1b = *reinterpret_cast<const float4*>(mrow + 104);
        pc0  = *reinterpret_cast<const float4*>(crow);
        pc1  = *reinterpret_cast<const float4*>(crow + 4);
        pc2  = *reinterpret_cast<const float4*>(crow + 8);
        pc3  = *reinterpret_cast<const float4*>(crow + 12);

        // ---- H1: chunks 0..5 (steps 0..47) -> slots 0..47 ----
#pragma unroll 1
        for (int ch = 0; ch < 6; ch++) {
            float4 z0a = pz0a, z0b = pz0b, z1a = pz1a, z1b = pz1b;
            float4 c0 = pc0, c1 = pc1, c2 = pc2, c3 = pc3;
            const int s0n = (ch + 1) * 8;
            pz0a = *reinterpret_cast<const float4*>(mrow + s0n);
            pz0b = *reinterpret_cast<const float4*>(mrow + s0n + 4);
            pz1a = *reinterpret_cast<const float4*>(mrow + 100 + s0n);
            pz1b = *reinterpret_cast<const float4*>(mrow + 104 + s0n);
            pc0  = *reinterpret_cast<const float4*>(crow + 2 * s0n);
            pc1  = *reinterpret_cast<const float4*>(crow + 2 * s0n + 4);
            pc2  = *reinterpret_cast<const float4*>(crow + 2 * s0n + 8);
            pc3  = *reinterpret_cast<const float4*>(crow + 2 * s0n + 12);
            run_chunk8(s, c, stage_f, ch * 8, z0a, z0b, z1a, z1b, c0, c1, c2, c3);
        }
    }

    __syncthreads();                          // H1 staging complete
    flush_half<12>(fsrc, fpp, fps, fpc, fh, 0);
    __syncthreads();                          // staging reusable

    if (comp) {
        // ---- H2: chunks 6..11 (steps 48..95) -> slots 0..47; tail -> 48..51 ----
#pragma unroll 1
        for (int ch = 6; ch < 12; ch++) {
            float4 z0a = pz0a, z0b = pz0b, z1a = pz1a, z1b = pz1b;
            float4 c0 = pc0, c1 = pc1, c2 = pc2, c3 = pc3;
            if (ch < 11) {
                const int s0n = (ch + 1) * 8;
                pz0a = *reinterpret_cast<const float4*>(mrow + s0n);
                pz0b = *reinterpret_cast<const float4*>(mrow + s0n + 4);
                pz1a = *reinterpret_cast<const float4*>(mrow + 100 + s0n);
                pz1b = *reinterpret_cast<const float4*>(mrow + 104 + s0n);
                pc0  = *reinterpret_cast<const float4*>(crow + 2 * s0n);
                pc1  = *reinterpret_cast<const float4*>(crow + 2 * s0n + 4);
                pc2  = *reinterpret_cast<const float4*>(crow + 2 * s0n + 8);
                pc3  = *reinterpret_cast<const float4*>(crow + 2 * s0n + 12);
            } else {
                pz0a = *reinterpret_cast<const float4*>(mrow + 96);
                pz1a = *reinterpret_cast<const float4*>(mrow + 196);
                pc0  = *reinterpret_cast<const float4*>(crow + 192);
                pc1  = *reinterpret_cast<const float4*>(crow + 196);
            }
            run_chunk8(s, c, stage_f, (ch - 6) * 8, z0a, z0b, z1a, z1b, c0, c1, c2, c3);
        }
        // tail: 4 steps -> slot 48
        {
            float buf[16][4];
            ukf_step(s, c, pz0a.x, pz1a.x, pc0.x, pc0.y, buf, 0);
            ukf_step(s, c, pz0a.y, pz1a.y, pc0.z, pc0.w, buf, 1);
            ukf_step(s, c, pz0a.z, pz1a.z, pc1.x, pc1.y, buf, 2);
            ukf_step(s, c, pz0a.w, pz1a.w, pc1.z, pc1.w, buf, 3);
            stage4(stage_f, 48, buf);
        }
    }

    __syncthreads();                          // H2 staging complete
    flush_half<13>(fsrc, fpp, fps, fpc, fh, 48);
}

extern "C" void kernel_launch(void* const* d_in, const int* in_sizes, int n_in,
                              void* d_out, int out_size)
{
    const float* meas  = (const float*)d_in[0];
    const float* state = (const float*)d_in[1];
    const float* cov   = (const float*)d_in[2];
    const float* ctrl  = (const float*)d_in[3];
    const float* Q     = (const float*)d_in[4];
    const float* R     = (const float*)d_in[5];

    float* out    = (float*)d_out;
    float* preds  = out;                         // 16384*2*100
    float* states = preds  + (size_t)NB * 200;   // 16384*4*100
    float* covs   = states + (size_t)NB * 400;   // 16384*16*100

    static int smem_set = 0;
    if (!smem_set) {
        cudaFuncSetAttribute(ukf_kernel,
                             cudaFuncAttributeMaxDynamicSharedMemorySize, SMEM_BYTES);
        smem_set = 1;
    }

    ukf_kernel<<<NB / FPB, THREADS, SMEM_BYTES>>>(meas, state, cov, ctrl, Q, R,
                                                  preds, states, covs);
}